// round 9
// baseline (speedup 1.0000x reference)
#include <cuda_runtime.h>
#include <cstdint>

#define B_IMG 16
#define HGT 1024
#define WID 1024
#define HW (1u << 20)
#define CAP (1 << 17)
#define NEG_INF __int_as_float(0xff800000)

// ---------------- scratch ----------------
__device__ float g_R[(size_t)B_IMG * HW];
__device__ int   g_RmaxBits[B_IMG];
__device__ int   g_count[B_IMG];
__device__ unsigned long long g_candKey[B_IMG][CAP];  // (valBits<<32)|(~idx)

__global__ void initK() {
    int t = threadIdx.x;
    if (t < B_IMG) { g_RmaxBits[t] = 0; g_count[t] = 0; }
}

__device__ __forceinline__ float4 ld4(const float* p) { return *(const float4*)p; }
__device__ __forceinline__ void st4(float* p, float4 v) { *(float4*)p = v; }
__device__ __forceinline__ float4 max4(float4 a, float4 b) {
    return make_float4(fmaxf(a.x, b.x), fmaxf(a.y, b.y), fmaxf(a.z, b.z), fmaxf(a.w, b.w));
}

// 7-tap horizontal box sum of p[0..9] -> 4 outputs
__device__ __forceinline__ float4 hsum7arr(const float* p) {
    float c = (p[3] + p[4]) + (p[5] + p[6]);
    return make_float4(((p[0] + p[1]) + p[2]) + c,
                       (p[1] + p[2]) + c + p[7],
                       p[2] + c + (p[7] + p[8]),
                       c + ((p[7] + p[8]) + p[9]));
}

// 15-tap horizontal max for 4 adjacent outputs from 18 consecutive values
__device__ __forceinline__ float4 hmax15(float4 A, float4 B, float4 C, float4 D, float4 E) {
    float common = fmaxf(fmaxf(fmaxf(fmaxf(A.w, B.x), fmaxf(B.y, B.z)), B.w),
                   fmaxf(fmaxf(fmaxf(C.x, C.y), fmaxf(C.z, C.w)),
                         fmaxf(D.x, fmaxf(D.y, D.z))));            // v3..v14
    float4 r;
    r.x = fmaxf(common, fmaxf(fmaxf(A.x, A.y), A.z));              // v0..v14
    r.y = fmaxf(common, fmaxf(fmaxf(A.y, A.z), D.w));              // v1..v15
    r.z = fmaxf(common, fmaxf(fmaxf(A.z, D.w), E.x));              // v2..v16
    r.w = fmaxf(common, fmaxf(fmaxf(D.w, E.x), E.y));              // v3..v17
    return r;
}

// ---------------- fused response kernel: 32 wide x 64 tall output tile ----------------
// Smem arena (floats):
//   S   @ [0, 2880)      72x40 quantized image tile (dead after phase 1.5)
//   VB  @ [2880, 5680)   70x40 vertical [1,2,1] blur
//   VD  @ [5680, 8480)   70x40 vertical [-1,0,1] diff
//   Hxx @ [0, 2240)      70x32 (reuses dead S)
//   Hyy @ [8480, 10720)
//   Hxy @ [10720, 12960)
#define CR_SMEM_FLOATS 12960
__global__ void __launch_bounds__(256) computeR(const float* __restrict__ img) {
    const int b  = blockIdx.z;
    const int X0 = blockIdx.x * 32;
    const int Y0 = blockIdx.y * 64;

    extern __shared__ __align__(16) float buf[];
    float (*S)[40]   = (float(*)[40])(buf);
    float (*VB)[40]  = (float(*)[40])(buf + 2880);
    float (*VD)[40]  = (float(*)[40])(buf + 5680);
    float (*Hxx)[32] = (float(*)[32])(buf);
    float (*Hyy)[32] = (float(*)[32])(buf + 8480);
    float (*Hxy)[32] = (float(*)[32])(buf + 10720);
    __shared__ float warpMax[8];

    const float* im = img + (size_t)b * HW;
    const int tid = threadIdx.x;
    const bool interior = (blockIdx.x > 0) & (blockIdx.x < 31) &
                          (blockIdx.y > 0) & (blockIdx.y < 15);

    // phase 1: load + quantize image with 4-halo (72x40)
    if (interior) {
        const float* p0 = im + (size_t)(Y0 - 4) * WID + (X0 - 4);
        for (int i = tid; i < 72 * 40; i += 256) {
            int r = i / 40, c = i - r * 40;
            float t = p0[r * WID + c];
            S[r][c] = fminf(fmaxf(floorf(t * 255.0f), 0.0f), 255.0f) / 255.0f;
        }
    } else {
        for (int i = tid; i < 72 * 40; i += 256) {
            int r = i / 40, c = i - r * 40;
            int gy = Y0 - 4 + r, gx = X0 - 4 + c;
            float v = 0.0f;
            if (gy >= 0 && gy < HGT && gx >= 0 && gx < WID) {
                float t = im[gy * WID + gx];
                v = fminf(fmaxf(floorf(t * 255.0f), 0.0f), 255.0f) / 255.0f;
            }
            S[r][c] = v;
        }
    }
    __syncthreads();

    // phase 1.5: separable sobel stage-1 (vertical blur + diff), 70 rows x 10 chunks
    for (int i = tid; i < 700; i += 256) {
        int r = i / 10, c0 = (i - r * 10) * 4;
        float4 x0 = ld4(&S[r][c0]);
        float4 x1 = ld4(&S[r + 1][c0]);
        float4 x2 = ld4(&S[r + 2][c0]);
        float4 vb, vd;
        vb.x = x0.x + 2.0f * x1.x + x2.x;  vd.x = x2.x - x0.x;
        vb.y = x0.y + 2.0f * x1.y + x2.y;  vd.y = x2.y - x0.y;
        vb.z = x0.z + 2.0f * x1.z + x2.z;  vd.z = x2.z - x0.z;
        vb.w = x0.w + 2.0f * x1.w + x2.w;  vd.w = x2.w - x0.w;
        st4(&VB[r][c0], vb);
        st4(&VD[r][c0], vd);
    }
    __syncthreads();

    // phase 2: ix/iy from VB/VD, products, horizontal 7-sum. 560 tasks.
    for (int i = tid; i < 560; i += 256) {
        int r = i >> 3, c0 = (i & 7) << 2;
        float4 B0 = ld4(&VB[r][c0]), B1 = ld4(&VB[r][c0 + 4]), B2 = ld4(&VB[r][c0 + 8]);
        float4 D0 = ld4(&VD[r][c0]), D1 = ld4(&VD[r][c0 + 4]), D2 = ld4(&VD[r][c0 + 8]);
        float bb[12] = {B0.x,B0.y,B0.z,B0.w, B1.x,B1.y,B1.z,B1.w, B2.x,B2.y,B2.z,B2.w};
        float dd[12] = {D0.x,D0.y,D0.z,D0.w, D1.x,D1.y,D1.z,D1.w, D2.x,D2.y,D2.z,D2.w};
        float ix[10], iy[10];
#pragma unroll
        for (int j = 0; j < 10; j++) {
            ix[j] = bb[j + 2] - bb[j];
            iy[j] = dd[j] + 2.0f * dd[j + 1] + dd[j + 2];
        }
        if (!interior) {
            int py = Y0 - 3 + r;
            float rowOK = (py >= 0 && py < HGT) ? 1.0f : 0.0f;
#pragma unroll
            for (int j = 0; j < 10; j++) {
                int gx = X0 + c0 - 3 + j;
                float m = (gx >= 0 && gx < WID) ? rowOK : 0.0f;
                ix[j] *= m; iy[j] *= m;
            }
        }
        float p[10];
#pragma unroll
        for (int j = 0; j < 10; j++) p[j] = ix[j] * ix[j];
        st4(&Hxx[r][c0], hsum7arr(p));
#pragma unroll
        for (int j = 0; j < 10; j++) p[j] = iy[j] * iy[j];
        st4(&Hyy[r][c0], hsum7arr(p));
#pragma unroll
        for (int j = 0; j < 10; j++) p[j] = ix[j] * iy[j];
        st4(&Hxy[r][c0], hsum7arr(p));
    }
    __syncthreads();

    // phase 3: warp-sliding vertical 7-sum. Each warp owns 8 output rows x 32 cols;
    // lane = column (scalar LDS.32, conflict-free). Each H row loaded exactly once,
    // box sum maintained with a 7-deep register ring.
    float localMax = 0.0f;
    {
        const int lane = tid & 31, w = tid >> 5;
        const int base = w << 3;                         // output rows base..base+7
        float rxx[7], ryy[7], rxy[7];
        float sxx = 0.0f, syy = 0.0f, sxy = 0.0f;
#pragma unroll
        for (int k = 0; k < 7; k++) {
            rxx[k] = Hxx[base + k][lane]; sxx += rxx[k];
            ryy[k] = Hyy[base + k][lane]; syy += ryy[k];
            rxy[k] = Hxy[base + k][lane]; sxy += rxy[k];
        }
        float* outp = &g_R[((size_t)b << 20) + (size_t)(Y0 + base) * WID + (X0 + lane)];
#pragma unroll
        for (int o = 0; o < 8; o++) {
            float ht = 0.5f * (sxx + syy), dd = 0.5f * (sxx - syy);
            float R = ht - sqrtf(dd * dd + sxy * sxy);
            outp[(size_t)o * WID] = R;
            localMax = fmaxf(localMax, R);
            if (o < 7) {
                float n;
                n = Hxx[base + o + 7][lane]; sxx += n - rxx[o]; rxx[o] = n;
                n = Hyy[base + o + 7][lane]; syy += n - ryy[o]; ryy[o] = n;
                n = Hxy[base + o + 7][lane]; sxy += n - rxy[o]; rxy[o] = n;
            }
        }
    }

#pragma unroll
    for (int o = 16; o > 0; o >>= 1)
        localMax = fmaxf(localMax, __shfl_xor_sync(0xffffffffu, localMax, o));
    if ((tid & 31) == 0) warpMax[tid >> 5] = localMax;
    __syncthreads();
    if (tid == 0) {
        float m = warpMax[0];
#pragma unroll
        for (int i = 1; i < 8; i++) m = fmaxf(m, warpMax[i]);
        atomicMax(&g_RmaxBits[b], __float_as_int(m));
    }
}

// ---------------- fused 15x15 NMS + threshold + collect: 32x64 tile ----------------
__global__ void __launch_bounds__(256) nmsCollect() {
    const int b  = blockIdx.z;
    const int X0 = blockIdx.x * 32;
    const int Y0 = blockIdx.y * 64;

    __shared__ __align__(16) float sh[78][48];   // gy=Y0-7+r, gx=X0-7+c
    __shared__ __align__(16) float hm[78][32];
    __shared__ float shThr;
    const int tid = threadIdx.x;
    const float* Rb = g_R + ((size_t)b << 20);
    const bool interior = (blockIdx.x > 0) & (blockIdx.x < 31) &
                          (blockIdx.y > 0) & (blockIdx.y < 15);

    if (interior) {
        const float* p0 = Rb + (size_t)(Y0 - 7) * WID + (X0 - 7);
        for (int i = tid; i < 78 * 48; i += 256) {
            int r = i / 48, c = i - r * 48;
            sh[r][c] = (c < 46) ? p0[r * WID + c] : NEG_INF;
        }
    } else {
        for (int i = tid; i < 78 * 48; i += 256) {
            int r = i / 48, c = i - r * 48;
            int gy = Y0 - 7 + r, gx = X0 - 7 + c;
            sh[r][c] = (c < 46 && gy >= 0 && gy < HGT && gx >= 0 && gx < WID)
                       ? Rb[(size_t)gy * WID + gx] : NEG_INF;
        }
    }
    if (tid == 0) shThr = 0.3f * __int_as_float(g_RmaxBits[b]);
    __syncthreads();

    // horizontal 15-max: 78 rows x 8 chunks
    for (int i = tid; i < 624; i += 256) {
        int r = i >> 3, c0 = (i & 7) << 2;
        st4(&hm[r][c0], hmax15(ld4(&sh[r][c0]),      ld4(&sh[r][c0 + 4]),
                               ld4(&sh[r][c0 + 8]),  ld4(&sh[r][c0 + 12]),
                               ld4(&sh[r][c0 + 16])));
    }
    __syncthreads();

    // vertical 15-max: 4-row window sharing. common = rows ly+3..ly+14 serves 4 outputs.
    const float thr = shThr;
    if (tid < 128) {
        int c0 = (tid & 7) << 2, ly = (tid >> 3) << 2;       // 16 groups x 4 rows
        float4 e0 = ld4(&hm[ly][c0]);
        float4 e1 = ld4(&hm[ly + 1][c0]);
        float4 e2 = ld4(&hm[ly + 2][c0]);
        float4 com = ld4(&hm[ly + 3][c0]);
#pragma unroll
        for (int k = 4; k < 15; k++) com = max4(com, ld4(&hm[ly + k][c0]));
        float4 f0 = ld4(&hm[ly + 15][c0]);
        float4 f1 = ld4(&hm[ly + 16][c0]);
        float4 f2 = ld4(&hm[ly + 17][c0]);
        float4 pool[4] = {
            max4(com, max4(e0, max4(e1, e2))),
            max4(com, max4(e1, max4(e2, f0))),
            max4(com, max4(e2, max4(f0, f1))),
            max4(com, max4(f0, max4(f1, f2))) };
#pragma unroll
        for (int o = 0; o < 4; o++) {
            int y = Y0 + ly + o;
            const float* cenRow = &sh[ly + o + 7][c0 + 7];
            float pl[4] = { pool[o].x, pool[o].y, pool[o].z, pool[o].w };
#pragma unroll
            for (int j = 0; j < 4; j++) {
                float rv = cenRow[j];
                if (rv >= pl[j] && rv >= thr) {
                    unsigned int idx = (unsigned int)(y * WID + (X0 + c0 + j));
                    int pos = atomicAdd(&g_count[b], 1);
                    if (pos < CAP)
                        g_candKey[b][pos] = ((unsigned long long)__float_as_uint(rv) << 32)
                                          | (unsigned long long)(0xFFFFFFFFu - idx);
                }
            }
        }
    }
}

// ---------------- exact per-image top-K: MSD radix select, warp-shuffle scan ----------------
__global__ void __launch_bounds__(512) selectK(float* __restrict__ out, const int* __restrict__ topkPtr) {
    const int b   = blockIdx.x;
    const int tid = threadIdx.x;
    const int topK = *topkPtr;
    int n = g_count[b]; if (n > CAP) n = CAP;

    __shared__ int hist[256];
    __shared__ int warpSum[8];
    __shared__ unsigned long long shK;
    __shared__ int shRem, shDone;

    if (tid == 0) { shK = 0ull; shRem = topK; shDone = (n <= topK) ? 1 : 0; }
    __syncthreads();

    for (int byte = 7; byte >= 0; byte--) {
        if (shDone) break;
        if (tid < 256) hist[tid] = 0;
        __syncthreads();
        const unsigned long long pref = shK;
        const int shift = byte * 8;
        for (int i = tid; i < n; i += 512) {
            unsigned long long key = g_candKey[b][i];
            bool match = (byte == 7) || ((key >> (shift + 8)) == (pref >> (shift + 8)));
            if (match) atomicAdd(&hist[(int)((key >> shift) & 255)], 1);
        }
        __syncthreads();
        int h = 0, v = 0;
        if (tid < 256) {
            h = hist[tid];
            v = h;
            int lane = tid & 31;
#pragma unroll
            for (int off = 1; off < 32; off <<= 1) {
                int t = __shfl_down_sync(0xffffffffu, v, off);
                if (lane + off < 32) v += t;
            }
            if (lane == 0) warpSum[tid >> 5] = v;
        }
        __syncthreads();
        if (tid < 256) {
            int add = 0;
            for (int w = (tid >> 5) + 1; w < 8; w++) add += warpSum[w];
            v += add;                       // inclusive suffix sum from bin tid
            int here = v, above = v - h;
            int rem = shRem;
            if (here >= rem && above < rem) {   // unique boundary bin
                int inBin = rem - above;
                int cnt   = h;
                shK = pref | ((unsigned long long)(unsigned int)tid << shift);
                if (inBin == cnt || byte == 0) shDone = 1;
                else shRem = inBin;
            }
        }
        __syncthreads();
    }

    const unsigned long long K = (n <= topK) ? 0ull : shK;
    for (int i = tid; i < n; i += 512) {
        unsigned long long key = g_candKey[b][i];
        if (key >= K) {
            unsigned int idx = 0xFFFFFFFFu - (unsigned int)(key & 0xFFFFFFFFull);
            out[((size_t)b << 20) + idx] = 1.0f;
        }
    }
}

// ---------------- launch ----------------
extern "C" void kernel_launch(void* const* d_in, const int* in_sizes, int n_in,
                              void* d_out, int out_size) {
    const float* img  = (const float*)d_in[0];
    const int*   topk = (const int*)d_in[1];
    float*       out  = (float*)d_out;

    cudaFuncSetAttribute(computeR, cudaFuncAttributeMaxDynamicSharedMemorySize,
                         CR_SMEM_FLOATS * (int)sizeof(float));

    cudaMemsetAsync(d_out, 0, (size_t)out_size * sizeof(float), 0);
    initK<<<1, 32>>>();
    computeR<<<dim3(32, 16, B_IMG), 256, CR_SMEM_FLOATS * sizeof(float)>>>(img);
    nmsCollect<<<dim3(32, 16, B_IMG), 256>>>();
    selectK<<<B_IMG, 512>>>(out, topk);
}